// round 11
// baseline (speedup 1.0000x reference)
#include <cuda_runtime.h>
#include <cuda_bf16.h>
#include <cstdint>

#define D 128
#define NMAX 100000
#define EMAX 1600000

// ---------------- scratch (no allocations allowed) ----------------
__device__ float g_h1[(size_t)NMAX * D];
__device__ float g_h2[(size_t)NMAX * D];
__device__ float g_hn[(size_t)NMAX * D];
__device__ int   g_deg[NMAX];
__device__ int   g_off[NMAX + 1];
__device__ int   g_pos[NMAX];
__device__ int   g_csr[EMAX];
__device__ float g_inv[NMAX];
// transposed bf16-split weights: [l][n][k], k = 0..255 (Ws then Wn)
__device__ unsigned short g_wt_hi[3 * 128 * 256];
__device__ unsigned short g_wt_lo[3 * 128 * 256];

// ---------------- helpers ----------------
__device__ __forceinline__ uint32_t smem_u32(const void* p) {
    uint32_t a;
    asm("{ .reg .u64 t; cvta.to.shared.u64 t, %1; cvt.u32.u64 %0, t; }" : "=r"(a) : "l"(p));
    return a;
}
__device__ __forceinline__ uint32_t pack_hi2(float a, float b) {
    return (__float_as_uint(a) >> 16) | (__float_as_uint(b) & 0xffff0000u);
}
__device__ __forceinline__ uint32_t bf16x2_rn(float lo, float hi) {
    uint32_t d;
    asm("cvt.rn.bf16x2.f32 %0, %1, %2;" : "=r"(d) : "f"(hi), "f"(lo));
    return d;
}
__device__ __forceinline__ float trunc_hi(float x) {
    return __uint_as_float(__float_as_uint(x) & 0xffff0000u);
}

#define LDSM4(r0, r1, r2, r3, addr)                                           \
    asm volatile("ldmatrix.sync.aligned.m8n8.x4.shared.b16 {%0,%1,%2,%3}, [%4];" \
                 : "=r"(r0), "=r"(r1), "=r"(r2), "=r"(r3) : "r"(addr))

__device__ __forceinline__ void mma_bf16(float (&c)[4], const uint32_t (&a)[4],
                                         uint32_t b0, uint32_t b1) {
    asm volatile(
        "mma.sync.aligned.m16n8k16.row.col.f32.bf16.bf16.f32 "
        "{%0,%1,%2,%3}, {%4,%5,%6,%7}, {%8,%9}, {%0,%1,%2,%3};"
        : "+f"(c[0]), "+f"(c[1]), "+f"(c[2]), "+f"(c[3])
        : "r"(a[0]), "r"(a[1]), "r"(a[2]), "r"(a[3]), "r"(b0), "r"(b1));
}

// ---------------- CSR build ----------------
__global__ void k_zero_deg(int n) {
    int i = blockIdx.x * blockDim.x + threadIdx.x;
    if (i < n) g_deg[i] = 0;
}
__global__ void k_count(const int* __restrict__ dst, int e) {
    int i = blockIdx.x * blockDim.x + threadIdx.x;
    if (i < e) atomicAdd(&g_deg[dst[i]], 1);
}
__device__ __forceinline__ int wscan(int v, int lane) {
#pragma unroll
    for (int s = 1; s < 32; s <<= 1) {
        int t = __shfl_up_sync(0xffffffffu, v, s);
        if (lane >= s) v += t;
    }
    return v;
}
__global__ void k_scan(int n) {
    __shared__ int wsum[32];
    __shared__ int s_carry;
    int lane = threadIdx.x & 31, wid = threadIdx.x >> 5;
    if (threadIdx.x == 0) s_carry = 0;
    __syncthreads();
    for (int base = 0; base < n; base += 1024) {
        int i = base + (int)threadIdx.x;
        int d = (i < n) ? g_deg[i] : 0;
        int incl = wscan(d, lane);
        if (lane == 31) wsum[wid] = incl;
        __syncthreads();
        if (wid == 0) wsum[lane] = wscan(wsum[lane], lane);
        __syncthreads();
        int bi = incl + (wid ? wsum[wid - 1] : 0);
        int carry = s_carry;
        if (i < n) {
            int excl = carry + bi - d;
            g_off[i] = excl; g_pos[i] = excl;
            g_inv[i] = 1.0f / fmaxf((float)d, 1.0f);
        }
        __syncthreads();
        if (threadIdx.x == 1023) s_carry = carry + bi;
        __syncthreads();
    }
    if (threadIdx.x == 0) g_off[n] = s_carry;
}
__global__ void k_fill(const int* __restrict__ src, const int* __restrict__ dst, int e) {
    int i = blockIdx.x * blockDim.x + threadIdx.x;
    if (i < e) {
        int p = atomicAdd(&g_pos[dst[i]], 1);
        g_csr[p] = src[i];
    }
}

// ---------------- weight transpose + bf16 split ----------------
__global__ void k_wt(const float* __restrict__ Ws, const float* __restrict__ Wn) {
    int i = blockIdx.x * blockDim.x + threadIdx.x;
    if (i >= 3 * 256 * 128) return;
    int l = i / (256 * 128);
    int rem = i % (256 * 128);
    int k = rem / 128;
    int nn = rem % 128;
    float w = (k < 128) ? Ws[(l * 128 + k) * 128 + nn]
                        : Wn[(l * 128 + (k - 128)) * 128 + nn];
    float hf = trunc_hi(w);
    float lf = w - hf;
    size_t o = ((size_t)(l * 128 + nn)) * 256 + k;
    g_wt_hi[o] = (unsigned short)(__float_as_uint(w) >> 16);
    __nv_bfloat16 lb = __float2bfloat16(lf);
    g_wt_lo[o] = *(unsigned short*)&lb;
}

// ---------------- neighbor mean (warp per node, float4 per lane) ----------------
__global__ void k_agg(const float* __restrict__ xin, int sel, int n) {
    const float* hin = (sel == 0) ? xin : ((sel == 1) ? g_h1 : g_h2);
    int w = (blockIdx.x * blockDim.x + threadIdx.x) >> 5;
    if (w >= n) return;
    int lane = threadIdx.x & 31;
    int beg = g_off[w], end = g_off[w + 1];
    const float4* h4 = (const float4*)hin;
    float4 a0 = make_float4(0.f, 0.f, 0.f, 0.f);
    float4 a1 = make_float4(0.f, 0.f, 0.f, 0.f);
    int ei = beg;
    for (; ei + 1 < end; ei += 2) {
        int u0 = __ldg(&g_csr[ei]);
        int u1 = __ldg(&g_csr[ei + 1]);
        float4 v0 = h4[(size_t)u0 * 32 + lane];
        float4 v1 = h4[(size_t)u1 * 32 + lane];
        a0.x += v0.x; a0.y += v0.y; a0.z += v0.z; a0.w += v0.w;
        a1.x += v1.x; a1.y += v1.y; a1.z += v1.z; a1.w += v1.w;
    }
    if (ei < end) {
        int u = __ldg(&g_csr[ei]);
        float4 v = h4[(size_t)u * 32 + lane];
        a0.x += v.x; a0.y += v.y; a0.z += v.z; a0.w += v.w;
    }
    float s = g_inv[w];
    float4 o;
    o.x = (a0.x + a1.x) * s; o.y = (a0.y + a1.y) * s;
    o.z = (a0.z + a1.z) * s; o.w = (a0.w + a1.w) * s;
    ((float4*)g_hn)[(size_t)w * 32 + lane] = o;
}

// ---------------- HMMA (mma.sync) bf16-split GEMM ----------------
// SMEM: A_hi/A_lo full K=256, 128 rows, pitch 528B (264 bf16, conflict-free
// ldmatrix); B_hi/B_lo one K=128 phase, 128 n-rows, pitch 272B.
#define SM_AHI  0
#define SM_ALO  67584            // 128*528
#define SM_BHI  135168           // 2*67584
#define SM_BLO  169984           // +128*272
#define SM_TOTAL 204800          // +128*272

__global__ void __launch_bounds__(256, 1) k_mma(
    const float* __restrict__ x, float* __restrict__ dout,
    const float* __restrict__ bias, int sel, int n) {
    extern __shared__ char smem[];
    uint32_t sb = smem_u32(smem);
    int tid = threadIdx.x, wid = tid >> 5, lane = tid & 31;
    const float* A0 = (sel == 0) ? x : ((sel == 1) ? g_h1 : g_h2);
    float* out = (sel == 0) ? g_h1 : ((sel == 1) ? g_h2 : dout);
    int blockRow = blockIdx.x * 128;

    // ---- A convert: fp32 -> bf16 hi/lo into padded SMEM ----
    {
        int r = tid >> 1, half = tid & 1;
        int grow = blockRow + r;
        const float4* srcp = half ? (const float4*)g_hn : (const float4*)A0;
#pragma unroll 4
        for (int j = 0; j < 32; j++) {
            float4 v = (grow < n) ? srcp[(size_t)grow * 32 + j]
                                  : make_float4(0.f, 0.f, 0.f, 0.f);
            int kg = half * 128 + j * 4;
            uint32_t off = (uint32_t)r * 528u + (uint32_t)kg * 2u;
            uint32_t h01 = pack_hi2(v.x, v.y);
            uint32_t h23 = pack_hi2(v.z, v.w);
            float lx = v.x - trunc_hi(v.x), ly = v.y - trunc_hi(v.y);
            float lz = v.z - trunc_hi(v.z), lw = v.w - trunc_hi(v.w);
            *(uint2*)(smem + SM_AHI + off) = make_uint2(h01, h23);
            *(uint2*)(smem + SM_ALO + off) =
                make_uint2(bf16x2_rn(lx, ly), bf16x2_rn(lz, lw));
        }
    }

    // warp tile: rows wr..wr+32, cols wc..wc+64
    int wr = (wid & 3) * 32;
    int wc = (wid >> 2) * 64;
    // ldmatrix per-lane addresses
    uint32_t a_row = (uint32_t)(wr + (lane & 7) + ((lane >> 3) & 1) * 8);
    uint32_t aoff  = a_row * 528u + ((uint32_t)(lane >> 4) * 8u) * 2u;
    uint32_t b_n   = (uint32_t)(wc + (lane & 7) + ((lane >> 4) & 1) * 8);
    uint32_t boff  = b_n * 272u + (((uint32_t)(lane >> 3) & 1u) * 8u) * 2u;

    float acc[2][8][4];
#pragma unroll
    for (int mt = 0; mt < 2; mt++)
#pragma unroll
        for (int nb = 0; nb < 8; nb++)
#pragma unroll
            for (int c = 0; c < 4; c++) acc[mt][nb][c] = 0.f;

    for (int phase = 0; phase < 2; phase++) {
        if (phase) __syncthreads();   // previous phase's B reads complete
        // ---- load B phase (128 n-rows x 128 k), hi & lo ----
        {
            int nn = tid & 127, half = tid >> 7;
            const unsigned short* W = half ? g_wt_lo : g_wt_hi;
            const uint2* wp = (const uint2*)(W + ((size_t)(sel * 128 + nn)) * 256 + phase * 128);
            char* dstb = smem + (half ? SM_BLO : SM_BHI) + (uint32_t)nn * 272u;
#pragma unroll 4
            for (int j = 0; j < 32; j++) {
                uint2 v = __ldg(&wp[j]);
                *(uint2*)(dstb + j * 8) = v;
            }
        }
        __syncthreads();

#pragma unroll
        for (int ks = 0; ks < 8; ks++) {
            uint32_t kkA2 = (uint32_t)(phase * 128 + ks * 16) * 2u;
            uint32_t kkB2 = (uint32_t)(ks * 16) * 2u;
            uint32_t ah[2][4], al[2][4], bh[4][4], bl[4][4];
#pragma unroll
            for (int mt = 0; mt < 2; mt++) {
                uint32_t a = sb + SM_AHI + aoff + (uint32_t)mt * (16u * 528u) + kkA2;
                LDSM4(ah[mt][0], ah[mt][1], ah[mt][2], ah[mt][3], a);
                LDSM4(al[mt][0], al[mt][1], al[mt][2], al[mt][3], a + (SM_ALO - SM_AHI));
            }
#pragma unroll
            for (int p = 0; p < 4; p++) {
                uint32_t b = sb + SM_BHI + boff + (uint32_t)p * (16u * 272u) + kkB2;
                LDSM4(bh[p][0], bh[p][1], bh[p][2], bh[p][3], b);
                LDSM4(bl[p][0], bl[p][1], bl[p][2], bl[p][3], b + (SM_BLO - SM_BHI));
            }
#pragma unroll
            for (int mt = 0; mt < 2; mt++)
#pragma unroll
                for (int p = 0; p < 4; p++) {
                    mma_bf16(acc[mt][2 * p],     ah[mt], bh[p][0], bh[p][1]);
                    mma_bf16(acc[mt][2 * p + 1], ah[mt], bh[p][2], bh[p][3]);
                    mma_bf16(acc[mt][2 * p],     ah[mt], bl[p][0], bl[p][1]);
                    mma_bf16(acc[mt][2 * p + 1], ah[mt], bl[p][2], bl[p][3]);
                    mma_bf16(acc[mt][2 * p],     al[mt], bh[p][0], bh[p][1]);
                    mma_bf16(acc[mt][2 * p + 1], al[mt], bh[p][2], bh[p][3]);
                }
        }
    }

    // ---- epilogue: bias + relu, float2 stores ----
    int r0 = blockRow + wr + (lane >> 2);
#pragma unroll
    for (int mt = 0; mt < 2; mt++) {
        int row = r0 + mt * 16;
#pragma unroll
        for (int nb = 0; nb < 8; nb++) {
            int col = wc + nb * 8 + (lane & 3) * 2;
            float2 bb = __ldg((const float2*)(bias + col));
            if (row < n) {
                float2 o;
                o.x = fmaxf(acc[mt][nb][0] + bb.x, 0.f);
                o.y = fmaxf(acc[mt][nb][1] + bb.y, 0.f);
                *(float2*)(out + (size_t)row * 128 + col) = o;
            }
            if (row + 8 < n) {
                float2 o;
                o.x = fmaxf(acc[mt][nb][2] + bb.x, 0.f);
                o.y = fmaxf(acc[mt][nb][3] + bb.y, 0.f);
                *(float2*)(out + (size_t)(row + 8) * 128 + col) = o;
            }
        }
    }
}

// ---------------- launch ----------------
extern "C" void kernel_launch(void* const* d_in, const int* in_sizes, int n_in,
                              void* d_out, int out_size) {
    const float* x    = (const float*)d_in[0];
    const float* Ws   = (const float*)d_in[1];
    const float* Wn   = (const float*)d_in[2];
    const float* bias = (const float*)d_in[3];
    const int*   src  = (const int*)d_in[4];
    const int*   dst  = (const int*)d_in[5];
    int n = in_sizes[0] / D;
    int e = in_sizes[4];
    float* out = (float*)d_out;

    cudaFuncSetAttribute(k_mma, cudaFuncAttributeMaxDynamicSharedMemorySize, SM_TOTAL);

    k_zero_deg<<<(n + 255) / 256, 256>>>(n);
    k_count<<<(e + 255) / 256, 256>>>(dst, e);
    k_scan<<<1, 1024>>>(n);
    k_fill<<<(e + 255) / 256, 256>>>(src, dst, e);
    k_wt<<<(3 * 256 * 128 + 255) / 256, 256>>>(Ws, Wn);

    int gmm = (n + 127) / 128;
    for (int l = 0; l < 3; l++) {
        k_agg<<<(n * 32 + 255) / 256, 256>>>(x, l, n);
        k_mma<<<gmm, 256, SM_TOTAL>>>(x, out, bias + l * D, l, n);
    }
}